// round 1
// baseline (speedup 1.0000x reference)
#include <cuda_runtime.h>
#include <math.h>

// Problem constants
#define Bsz 2
#define Slen 2048
#define Dm 512
#define Hh 8
#define Aa 64
#define Ll 2
#define Tt 256
#define Mrows (Bsz*Slen)   // 4096
#define LN_EPS 1e-5f

// ---------------- scratch (device globals; no allocation allowed) ----------
__device__ float g_x[Mrows*Dm];            // running activations [B*S, D]
__device__ float g_q[Bsz*Hh*Slen*Aa];      // [B,H,S,A]
__device__ float g_k[Bsz*Hh*Slen*Aa];
__device__ float g_v[Bsz*Hh*Slen*Aa];
__device__ float g_heads[Mrows*Hh*Aa];     // [B,S,H*A]
__device__ float g_tmp[Mrows*Dm];
__device__ float g_h1[Mrows*Dm];

// ---------------------------------------------------------------------------
// QKV projection: for head h, out[b,h,s,a] = sum_d x[b,s,d] * W[h,d,a] + bias[h,a]
// grid = (H, Mrows/64, 3), block = 256. 64x64 tile, 4x4 microtile.
// ---------------------------------------------------------------------------
__global__ __launch_bounds__(256)
void qkv_kernel(const float* __restrict__ x,
                const float* __restrict__ Wq, const float* __restrict__ Wk,
                const float* __restrict__ Wv,
                const float* __restrict__ bq, const float* __restrict__ bk,
                const float* __restrict__ bv,
                float* __restrict__ Q, float* __restrict__ K, float* __restrict__ V)
{
    const float* W; const float* bias; float* out;
    int z = blockIdx.z;
    if (z == 0)      { W = Wq; bias = bq; out = Q; }
    else if (z == 1) { W = Wk; bias = bk; out = K; }
    else             { W = Wv; bias = bv; out = V; }

    const int h  = blockIdx.x;       // head (N-tile of width 64 == A)
    const int m0 = blockIdx.y * 64;

    __shared__ float As[16][64];     // [kk][m]
    __shared__ float Bs[16][64];     // [kk][a]

    const int tid = threadIdx.x;
    const int ty = tid / 16, tx = tid % 16;

    float acc[4][4] = {};
    const float* Wh = W + (size_t)h * Dm * Aa;  // element (d,a) at Wh[d*64 + a]

    for (int kt = 0; kt < Dm; kt += 16) {
        {   // A tile: 64 rows x 16 k, one float4 per thread
            int row = tid >> 2;          // 0..63
            int q4  = tid & 3;           // 0..3
            float4 va = *reinterpret_cast<const float4*>(&x[(size_t)(m0 + row) * Dm + kt + q4 * 4]);
            As[q4*4+0][row] = va.x; As[q4*4+1][row] = va.y;
            As[q4*4+2][row] = va.z; As[q4*4+3][row] = va.w;
        }
        {   // B tile: 16 k x 64 a, one float4 per thread
            int kk = tid >> 4;           // 0..15
            int a4 = tid & 15;           // 0..15
            float4 vb = *reinterpret_cast<const float4*>(&Wh[(size_t)(kt + kk) * Aa + a4 * 4]);
            Bs[kk][a4*4+0] = vb.x; Bs[kk][a4*4+1] = vb.y;
            Bs[kk][a4*4+2] = vb.z; Bs[kk][a4*4+3] = vb.w;
        }
        __syncthreads();
        #pragma unroll
        for (int kk = 0; kk < 16; kk++) {
            float a_[4], b_[4];
            #pragma unroll
            for (int i = 0; i < 4; i++) a_[i] = As[kk][ty*4 + i];
            #pragma unroll
            for (int j = 0; j < 4; j++) b_[j] = Bs[kk][tx*4 + j];
            #pragma unroll
            for (int i = 0; i < 4; i++)
                #pragma unroll
                for (int j = 0; j < 4; j++)
                    acc[i][j] = fmaf(a_[i], b_[j], acc[i][j]);
        }
        __syncthreads();
    }

    #pragma unroll
    for (int i = 0; i < 4; i++) {
        int m = m0 + ty*4 + i;
        int b_ = m / Slen, s = m % Slen;
        #pragma unroll
        for (int j = 0; j < 4; j++) {
            int a = tx*4 + j;
            out[(((size_t)(b_*Hh + h) * Slen) + s) * Aa + a] = acc[i][j] + bias[h*Aa + a];
        }
    }
}

// ---------------------------------------------------------------------------
// Generic tiled GEMM: C[M,N] = A[M,K] @ B[K,N] + bias[N]   (optional ReLU)
// grid = (N/64, M/64), block = 256.  M is always Mrows-compatible tiles.
// ---------------------------------------------------------------------------
__global__ __launch_bounds__(256)
void gemm_kernel(const float* __restrict__ Amat, const float* __restrict__ Bmat,
                 const float* __restrict__ bias, float* __restrict__ C,
                 int N, int Kd, int relu)
{
    const int n0 = blockIdx.x * 64;
    const int m0 = blockIdx.y * 64;

    __shared__ float As[16][64];   // [kk][m]
    __shared__ float Bs[16][64];   // [kk][n]

    const int tid = threadIdx.x;
    const int ty = tid / 16, tx = tid % 16;

    float acc[4][4] = {};

    for (int kt = 0; kt < Kd; kt += 16) {
        {
            int row = tid >> 2;
            int q4  = tid & 3;
            float4 va = *reinterpret_cast<const float4*>(&Amat[(size_t)(m0 + row) * Kd + kt + q4 * 4]);
            As[q4*4+0][row] = va.x; As[q4*4+1][row] = va.y;
            As[q4*4+2][row] = va.z; As[q4*4+3][row] = va.w;
        }
        {
            int kk = tid >> 4;
            int n4 = tid & 15;
            float4 vb = *reinterpret_cast<const float4*>(&Bmat[(size_t)(kt + kk) * N + n0 + n4 * 4]);
            Bs[kk][n4*4+0] = vb.x; Bs[kk][n4*4+1] = vb.y;
            Bs[kk][n4*4+2] = vb.z; Bs[kk][n4*4+3] = vb.w;
        }
        __syncthreads();
        #pragma unroll
        for (int kk = 0; kk < 16; kk++) {
            float a_[4], b_[4];
            #pragma unroll
            for (int i = 0; i < 4; i++) a_[i] = As[kk][ty*4 + i];
            #pragma unroll
            for (int j = 0; j < 4; j++) b_[j] = Bs[kk][tx*4 + j];
            #pragma unroll
            for (int i = 0; i < 4; i++)
                #pragma unroll
                for (int j = 0; j < 4; j++)
                    acc[i][j] = fmaf(a_[i], b_[j], acc[i][j]);
        }
        __syncthreads();
    }

    #pragma unroll
    for (int i = 0; i < 4; i++) {
        int m = m0 + ty*4 + i;
        #pragma unroll
        for (int j = 0; j < 4; j++) {
            int n = n0 + tx*4 + j;
            float v = acc[i][j] + bias[n];
            if (relu) v = fmaxf(v, 0.0f);
            C[(size_t)m * N + n] = v;
        }
    }
}

// ---------------------------------------------------------------------------
// Flash attention: per (b,h), 64-query-row tiles, online softmax over S=2048.
// block = 256 (16x16 threads, 4x4 microtiles). Dynamic smem = 3 * 64*65 floats.
// K-tile buffer is reused for the P (probability) tile.
// heads layout: [B, S, H*A] (concat-ready).
// ---------------------------------------------------------------------------
__global__ __launch_bounds__(256)
void flash_kernel(const float* __restrict__ Q, const float* __restrict__ K,
                  const float* __restrict__ V, float* __restrict__ heads)
{
    extern __shared__ float sm[];
    float* Qs  = sm;               // [64][65] query tile (row-major, row*65+k)
    float* KPs = sm + 64*65;       // [64][65] K tile, reused as P tile
    float* Vs  = sm + 2*64*65;     // [64][65]

    const int s0 = blockIdx.x * 64;
    const int h  = blockIdx.y;
    const int b  = blockIdx.z;

    const float* Qbh = Q + ((size_t)(b*Hh + h) * Slen) * Aa;
    const float* Kbh = K + ((size_t)(b*Hh + h) * Slen) * Aa;
    const float* Vbh = V + ((size_t)(b*Hh + h) * Slen) * Aa;

    const int tid = threadIdx.x;
    const int ty = tid / 16, tx = tid % 16;

    // Load Q tile (64x64 floats = 1024 float4; 4 per thread)
    #pragma unroll
    for (int it = 0; it < 4; it++) {
        int idx = tid + it * 256;         // 0..1023
        int r = idx >> 4, q4 = idx & 15;
        float4 vq = *reinterpret_cast<const float4*>(&Qbh[(size_t)(s0 + r) * Aa + q4 * 4]);
        Qs[r*65 + q4*4 + 0] = vq.x; Qs[r*65 + q4*4 + 1] = vq.y;
        Qs[r*65 + q4*4 + 2] = vq.z; Qs[r*65 + q4*4 + 3] = vq.w;
    }

    float m_run[4], l_run[4], O[4][4];
    #pragma unroll
    for (int i = 0; i < 4; i++) {
        m_run[i] = -INFINITY; l_run[i] = 0.0f;
        #pragma unroll
        for (int j = 0; j < 4; j++) O[i][j] = 0.0f;
    }
    const float scale = 0.125f;  // 1/sqrt(64)

    for (int c0 = 0; c0 < Slen; c0 += 64) {
        // Load K and V tiles
        #pragma unroll
        for (int it = 0; it < 4; it++) {
            int idx = tid + it * 256;
            int r = idx >> 4, q4 = idx & 15;
            float4 vk = *reinterpret_cast<const float4*>(&Kbh[(size_t)(c0 + r) * Aa + q4 * 4]);
            KPs[r*65 + q4*4 + 0] = vk.x; KPs[r*65 + q4*4 + 1] = vk.y;
            KPs[r*65 + q4*4 + 2] = vk.z; KPs[r*65 + q4*4 + 3] = vk.w;
            float4 vv = *reinterpret_cast<const float4*>(&Vbh[(size_t)(c0 + r) * Aa + q4 * 4]);
            Vs[r*65 + q4*4 + 0] = vv.x; Vs[r*65 + q4*4 + 1] = vv.y;
            Vs[r*65 + q4*4 + 2] = vv.z; Vs[r*65 + q4*4 + 3] = vv.w;
        }
        __syncthreads();

        // S = Q @ K^T (4x4 per thread)
        float sv[4][4] = {};
        #pragma unroll 8
        for (int kk = 0; kk < 64; kk++) {
            float a_[4], b_[4];
            #pragma unroll
            for (int i = 0; i < 4; i++) a_[i] = Qs[(ty*4 + i)*65 + kk];
            #pragma unroll
            for (int j = 0; j < 4; j++) b_[j] = KPs[(tx*4 + j)*65 + kk];
            #pragma unroll
            for (int i = 0; i < 4; i++)
                #pragma unroll
                for (int j = 0; j < 4; j++)
                    sv[i][j] = fmaf(a_[i], b_[j], sv[i][j]);
        }

        // Online softmax update (row groups: 16 threads with same ty share 4 rows)
        float m_new[4], fac[4], psum[4];
        #pragma unroll
        for (int i = 0; i < 4; i++) {
            float tmax = -INFINITY;
            #pragma unroll
            for (int j = 0; j < 4; j++) {
                sv[i][j] *= scale;
                tmax = fmaxf(tmax, sv[i][j]);
            }
            #pragma unroll
            for (int off = 8; off >= 1; off >>= 1)
                tmax = fmaxf(tmax, __shfl_xor_sync(0xffffffffu, tmax, off));
            m_new[i] = fmaxf(m_run[i], tmax);
            fac[i]   = __expf(m_run[i] - m_new[i]);
            float ps = 0.0f;
            #pragma unroll
            for (int j = 0; j < 4; j++) {
                float p = __expf(sv[i][j] - m_new[i]);
                sv[i][j] = p;
                ps += p;
            }
            #pragma unroll
            for (int off = 8; off >= 1; off >>= 1)
                ps += __shfl_xor_sync(0xffffffffu, ps, off);
            psum[i] = ps;
        }
        #pragma unroll
        for (int i = 0; i < 4; i++) {
            l_run[i] = l_run[i] * fac[i] + psum[i];
            m_run[i] = m_new[i];
            #pragma unroll
            for (int j = 0; j < 4; j++) O[i][j] *= fac[i];
        }

        __syncthreads();   // everyone done reading K before P overwrite
        #pragma unroll
        for (int i = 0; i < 4; i++)
            #pragma unroll
            for (int j = 0; j < 4; j++)
                KPs[(ty*4 + i)*65 + tx*4 + j] = sv[i][j];
        __syncthreads();

        // O += P @ V
        #pragma unroll 8
        for (int cc = 0; cc < 64; cc++) {
            float p_[4], v_[4];
            #pragma unroll
            for (int i = 0; i < 4; i++) p_[i] = KPs[(ty*4 + i)*65 + cc];
            #pragma unroll
            for (int j = 0; j < 4; j++) v_[j] = Vs[cc*65 + tx*4 + j];
            #pragma unroll
            for (int i = 0; i < 4; i++)
                #pragma unroll
                for (int j = 0; j < 4; j++)
                    O[i][j] = fmaf(p_[i], v_[j], O[i][j]);
        }
        __syncthreads();   // before reloading K/V tiles
    }

    // Normalize + write: heads[b, s, h*A + a]
    #pragma unroll
    for (int i = 0; i < 4; i++) {
        float inv = 1.0f / l_run[i];
        int s = s0 + ty*4 + i;
        #pragma unroll
        for (int j = 0; j < 4; j++) {
            int a = tx*4 + j;
            heads[(((size_t)b * Slen + s) * Hh + h) * Aa + a] = O[i][j] * inv;
        }
    }
}

// ---------------------------------------------------------------------------
// Fused residual-add + LayerNorm (in-place on x): x = LN(x + t) * g + beta
// grid = Mrows, block = 256 (each thread owns 2 of the 512 columns)
// ---------------------------------------------------------------------------
__global__ __launch_bounds__(256)
void addln_kernel(float* __restrict__ x, const float* __restrict__ t,
                  const float* __restrict__ g, const float* __restrict__ beta)
{
    const int r = blockIdx.x;
    const int tid = threadIdx.x;
    float v0 = x[(size_t)r*Dm + tid]       + t[(size_t)r*Dm + tid];
    float v1 = x[(size_t)r*Dm + 256 + tid] + t[(size_t)r*Dm + 256 + tid];

    float s  = v0 + v1;
    float ss = v0*v0 + v1*v1;
    #pragma unroll
    for (int off = 16; off >= 1; off >>= 1) {
        s  += __shfl_xor_sync(0xffffffffu, s,  off);
        ss += __shfl_xor_sync(0xffffffffu, ss, off);
    }
    __shared__ float red_s[8], red_ss[8];
    __shared__ float sm_mean, sm_rstd;
    int wid = tid >> 5, lane = tid & 31;
    if (lane == 0) { red_s[wid] = s; red_ss[wid] = ss; }
    __syncthreads();
    if (tid == 0) {
        float S = 0.0f, SS = 0.0f;
        #pragma unroll
        for (int w = 0; w < 8; w++) { S += red_s[w]; SS += red_ss[w]; }
        float mean = S * (1.0f / Dm);
        float var  = SS * (1.0f / Dm) - mean * mean;
        sm_mean = mean;
        sm_rstd = rsqrtf(var + LN_EPS);
    }
    __syncthreads();
    float mean = sm_mean, rstd = sm_rstd;
    x[(size_t)r*Dm + tid]       = (v0 - mean) * rstd * g[tid]       + beta[tid];
    x[(size_t)r*Dm + 256 + tid] = (v1 - mean) * rstd * g[256 + tid] + beta[256 + tid];
}

// ---------------------------------------------------------------------------
extern "C" void kernel_launch(void* const* d_in, const int* in_sizes, int n_in,
                              void* d_out, int out_size)
{
    const float* x    = (const float*)d_in[0];
    const float* Wq   = (const float*)d_in[1];
    const float* bq   = (const float*)d_in[2];
    const float* Wk   = (const float*)d_in[3];
    const float* bk   = (const float*)d_in[4];
    const float* Wv   = (const float*)d_in[5];
    const float* bv   = (const float*)d_in[6];
    const float* Wo   = (const float*)d_in[7];
    const float* bo   = (const float*)d_in[8];
    const float* ln1g = (const float*)d_in[9];
    const float* ln1b = (const float*)d_in[10];
    const float* W1   = (const float*)d_in[11];
    const float* b1   = (const float*)d_in[12];
    const float* W2   = (const float*)d_in[13];
    const float* b2   = (const float*)d_in[14];
    const float* ln2g = (const float*)d_in[15];
    const float* ln2b = (const float*)d_in[16];
    const float* Wp   = (const float*)d_in[17];
    const float* bp   = (const float*)d_in[18];

    float *gx, *gq, *gk, *gv, *gh, *gt, *g1;
    cudaGetSymbolAddress((void**)&gx, g_x);
    cudaGetSymbolAddress((void**)&gq, g_q);
    cudaGetSymbolAddress((void**)&gk, g_k);
    cudaGetSymbolAddress((void**)&gv, g_v);
    cudaGetSymbolAddress((void**)&gh, g_heads);
    cudaGetSymbolAddress((void**)&gt, g_tmp);
    cudaGetSymbolAddress((void**)&g1, g_h1);

    const int flash_smem = 3 * 64 * 65 * (int)sizeof(float);   // 49920 B
    cudaFuncSetAttribute(flash_kernel, cudaFuncAttributeMaxDynamicSharedMemorySize,
                         flash_smem);

    cudaMemcpyAsync(gx, x, (size_t)Mrows * Dm * sizeof(float),
                    cudaMemcpyDeviceToDevice);

    for (int l = 0; l < Ll; l++) {
        const float* Wq_l = Wq + (size_t)l * Hh * Dm * Aa;
        const float* Wk_l = Wk + (size_t)l * Hh * Dm * Aa;
        const float* Wv_l = Wv + (size_t)l * Hh * Dm * Aa;
        const float* bq_l = bq + (size_t)l * Hh * Aa;
        const float* bk_l = bk + (size_t)l * Hh * Aa;
        const float* bv_l = bv + (size_t)l * Hh * Aa;
        const float* Wo_l = Wo + (size_t)l * (Hh*Aa) * Dm;
        const float* bo_l = bo + (size_t)l * Dm;
        const float* W1_l = W1 + (size_t)l * Dm * Dm;
        const float* b1_l = b1 + (size_t)l * Dm;
        const float* W2_l = W2 + (size_t)l * Dm * Dm;
        const float* b2_l = b2 + (size_t)l * Dm;

        // QKV projections
        qkv_kernel<<<dim3(Hh, Mrows/64, 3), 256>>>(
            gx, Wq_l, Wk_l, Wv_l, bq_l, bk_l, bv_l, gq, gk, gv);

        // Flash attention -> heads [B,S,H*A]
        flash_kernel<<<dim3(Slen/64, Hh, Bsz), 256, flash_smem>>>(gq, gk, gv, gh);

        // Output projection
        gemm_kernel<<<dim3(Dm/64, Mrows/64), 256>>>(gh, Wo_l, bo_l, gt, Dm, Hh*Aa, 0);
        // AddNorm 1 (in-place on gx)
        addln_kernel<<<Mrows, 256>>>(gx, gt, ln1g + (size_t)l*Dm, ln1b + (size_t)l*Dm);

        // FFN
        gemm_kernel<<<dim3(Dm/64, Mrows/64), 256>>>(gx, W1_l, b1_l, g1, Dm, Dm, 1);
        gemm_kernel<<<dim3(Dm/64, Mrows/64), 256>>>(g1, W2_l, b2_l, gt, Dm, Dm, 0);
        // AddNorm 2
        addln_kernel<<<Mrows, 256>>>(gx, gt, ln2g + (size_t)l*Dm, ln2b + (size_t)l*Dm);
    }

    // Final projection to target_dim
    gemm_kernel<<<dim3(Tt/64, Mrows/64), 256>>>(gx, Wp, bp, (float*)d_out, Tt, Dm, 0);
}